// round 3
// baseline (speedup 1.0000x reference)
#include <cuda_runtime.h>
#include <cuda_bf16.h>
#include <cstdint>

// ---------------------------------------------------------------------------
// Problem constants
// ---------------------------------------------------------------------------
static constexpr int N_TOK = 2048;
static constexpr int H     = 4096;
static constexpr int V     = 32000;

// GEMM tiling (mma.sync path — sm_103 non-'a' target has no tcgen05)
static constexpr int BM = 128;
static constexpr int BN = 256;
static constexpr int BK = 64;               // bf16 elems = 128 B (SW128 atom row)
static constexpr int KITERS  = H / BK;      // 64
static constexpr int NSTAGES = 3;

static constexpr int A_BYTES     = BM * 128;           // 16 KB
static constexpr int B_BYTES     = BN * 128;           // 32 KB
static constexpr int STAGE_BYTES = A_BYTES + B_BYTES;  // 48 KB

static constexpr int SM_BIAS   = 0;                    // 256 floats = 1 KB
static constexpr int SM_STAGE0 = 1024;
static constexpr int SMEM_BYTES = SM_STAGE0 + NSTAGES * STAGE_BYTES; // 148480

// ---------------------------------------------------------------------------
// Device scratch (__device__ globals per allocation-free contract)
// ---------------------------------------------------------------------------
__device__ __align__(1024) __nv_bfloat16 g_Xs[(size_t)N_TOK * H];
__device__ __align__(1024) __nv_bfloat16 g_Xt[(size_t)N_TOK * H];
__device__ __align__(1024) __nv_bfloat16 g_Ws[(size_t)V * H];
__device__ __align__(1024) __nv_bfloat16 g_Wt[(size_t)V * H];
__device__ __align__(1024) float         g_Ls[(size_t)N_TOK * V];
__device__ __align__(1024) float         g_Lt[(size_t)N_TOK * V];
__device__               float           g_rows[N_TOK];

// ---------------------------------------------------------------------------
// PTX helpers (all sm_80/sm_75-level: valid on plain sm_103 target)
// ---------------------------------------------------------------------------
__device__ __forceinline__ uint32_t smem_u32(const void* p) {
    uint32_t a;
    asm("{ .reg .u64 t; cvta.to.shared.u64 t, %1; cvt.u32.u64 %0, t; }" : "=r"(a) : "l"(p));
    return a;
}

__device__ __forceinline__ void cp16(uint32_t dst, const void* src) {
    asm volatile("cp.async.cg.shared.global [%0], [%1], 16;" :: "r"(dst), "l"(src) : "memory");
}

__device__ __forceinline__ void cp_commit() {
    asm volatile("cp.async.commit_group;" ::: "memory");
}

template <int N>
__device__ __forceinline__ void cp_wait() {
    asm volatile("cp.async.wait_group %0;" :: "n"(N) : "memory");
}

__device__ __forceinline__ void ldsm4(uint32_t& r0, uint32_t& r1, uint32_t& r2, uint32_t& r3,
                                      uint32_t addr) {
    asm volatile("ldmatrix.sync.aligned.m8n8.x4.shared.b16 {%0,%1,%2,%3}, [%4];"
                 : "=r"(r0), "=r"(r1), "=r"(r2), "=r"(r3) : "r"(addr));
}

__device__ __forceinline__ void mma16816(float* c, const uint32_t* a, const uint32_t* b) {
    asm volatile(
        "mma.sync.aligned.m16n8k16.row.col.f32.bf16.bf16.f32 "
        "{%0,%1,%2,%3},{%4,%5,%6,%7},{%8,%9},{%0,%1,%2,%3};"
        : "+f"(c[0]), "+f"(c[1]), "+f"(c[2]), "+f"(c[3])
        : "r"(a[0]), "r"(a[1]), "r"(a[2]), "r"(a[3]), "r"(b[0]), "r"(b[1]));
}

__device__ __forceinline__ uint32_t sw128(uint32_t off) {
    return off ^ ((off >> 3) & 0x70);
}

// ---------------------------------------------------------------------------
// Kernel 1: fp32 -> bf16 (vectorized grid-stride)
// ---------------------------------------------------------------------------
__global__ void __launch_bounds__(256) conv_kernel(const float* __restrict__ src,
                                                   __nv_bfloat16* __restrict__ dst, int n4) {
    int i = blockIdx.x * blockDim.x + threadIdx.x;
    const int stride = gridDim.x * blockDim.x;
    const float4* s4 = (const float4*)src;
    uint2* d2 = (uint2*)dst;
    for (; i < n4; i += stride) {
        float4 v = s4[i];
        __nv_bfloat162 lo = __floats2bfloat162_rn(v.x, v.y);
        __nv_bfloat162 hi = __floats2bfloat162_rn(v.z, v.w);
        uint2 o;
        o.x = *(const uint32_t*)&lo;
        o.y = *(const uint32_t*)&hi;
        d2[i] = o;
    }
}

// ---------------------------------------------------------------------------
// Kernel 2: pipelined mma.sync GEMM + bias: out[m,v] = X[m,:] . W[v,:] + b[v]
// grid = (16 mtiles, 125 ntiles), 256 threads = 8 warps (2 m x 4 n), m64n64/warp
// ---------------------------------------------------------------------------
__global__ void __launch_bounds__(256, 1) gemm_bias_kernel(
    const __nv_bfloat16* __restrict__ X,
    const __nv_bfloat16* __restrict__ W,
    const float* __restrict__ bias,
    float* __restrict__ out)
{
    extern __shared__ __align__(1024) char smem[];
    const uint32_t sb = smem_u32(smem);
    const int tid  = threadIdx.x;
    const int wid  = tid >> 5;
    const int lane = tid & 31;
    const int wm   = wid & 1;        // warp m-block (0..1), 64 rows each
    const int wn   = wid >> 1;       // warp n-block (0..3), 64 cols each
    const int mtile = blockIdx.x;
    const int ntile = blockIdx.y;

    if (tid < BN / 4) {
        ((float4*)(smem + SM_BIAS))[tid] = ((const float4*)(bias + (size_t)ntile * BN))[tid];
    }

    const __nv_bfloat16* Abase = X + (size_t)mtile * BM * H;
    const __nv_bfloat16* Bbase = W + (size_t)ntile * BN * H;

    // stage loader: 256 threads, 16B chunks, SW128 swizzle
    auto load_stage = [&](int k) {
        const int s = k % NSTAGES;
        const uint32_t sa = sb + SM_STAGE0 + s * STAGE_BYTES;
        const __nv_bfloat16* Ak = Abase + k * BK;
        const __nv_bfloat16* Bk = Bbase + k * BK;
#pragma unroll
        for (int i = 0; i < BM * 8 / 256; i++) {        // 4 iters
            int c = tid + i * 256;
            int row = c >> 3, ch = c & 7;
            uint32_t off = row * 128 + ch * 16;
            cp16(sa + sw128(off), Ak + (size_t)row * H + ch * 8);
        }
#pragma unroll
        for (int i = 0; i < BN * 8 / 256; i++) {        // 8 iters
            int c = tid + i * 256;
            int row = c >> 3, ch = c & 7;
            uint32_t off = row * 128 + ch * 16;
            cp16(sa + A_BYTES + sw128(off), Bk + (size_t)row * H + ch * 8);
        }
    };

    // prologue: stages 0..NSTAGES-2
#pragma unroll
    for (int k = 0; k < NSTAGES - 1; k++) { load_stage(k); cp_commit(); }

    float acc[4][8][4];
#pragma unroll
    for (int mt = 0; mt < 4; mt++)
#pragma unroll
        for (int nt = 0; nt < 8; nt++)
#pragma unroll
            for (int j = 0; j < 4; j++) acc[mt][nt][j] = 0.f;

    const int lr  = lane & 15;        // ldmatrix row-within-16
    const int lbc = (lane >> 4) << 4; // ldmatrix byte-col half (0 or 16)

    for (int k = 0; k < KITERS; k++) {
        const int s = k % NSTAGES;
        cp_wait<NSTAGES - 2>();
        __syncthreads();

        // issue next stage's loads first (into slot consumed at iteration k-1)
        const int kn = k + NSTAGES - 1;
        if (kn < KITERS) load_stage(kn);
        cp_commit();

        const uint32_t abase = sb + SM_STAGE0 + s * STAGE_BYTES;
        const uint32_t bbase = abase + A_BYTES;

#pragma unroll
        for (int ks = 0; ks < BK / 16; ks++) {          // 4 k-steps of 16
            const int bc = ks * 32 + lbc;
            uint32_t af[4][4], bf[8][2];
#pragma unroll
            for (int mt = 0; mt < 4; mt++) {
                int row = wm * 64 + mt * 16 + lr;
                ldsm4(af[mt][0], af[mt][1], af[mt][2], af[mt][3],
                      abase + sw128((uint32_t)(row * 128 + bc)));
            }
#pragma unroll
            for (int nt2 = 0; nt2 < 4; nt2++) {
                int row = wn * 64 + nt2 * 16 + lr;
                uint32_t t0, t1, t2, t3;
                ldsm4(t0, t1, t2, t3, bbase + sw128((uint32_t)(row * 128 + bc)));
                bf[nt2 * 2][0] = t0; bf[nt2 * 2][1] = t2;
                bf[nt2 * 2 + 1][0] = t1; bf[nt2 * 2 + 1][1] = t3;
            }
#pragma unroll
            for (int mt = 0; mt < 4; mt++)
#pragma unroll
                for (int nt = 0; nt < 8; nt++)
                    mma16816(acc[mt][nt], af[mt], bf[nt]);
        }
    }

    // epilogue: bias add + fp32 store
    const float* bias_s = (const float*)(smem + SM_BIAS);
    const int gr = lane >> 2;         // accum row within 16-tile
    const int gc = (lane & 3) * 2;    // accum col pair within 8-tile
#pragma unroll
    for (int mt = 0; mt < 4; mt++) {
        const size_t r0 = (size_t)mtile * BM + wm * 64 + mt * 16 + gr;
        float* p0 = out + r0 * V + (size_t)ntile * BN + wn * 64;
        float* p1 = p0 + (size_t)8 * V;
#pragma unroll
        for (int nt = 0; nt < 8; nt++) {
            const int col = nt * 8 + gc;
            const float bx = bias_s[wn * 64 + col];
            const float by = bias_s[wn * 64 + col + 1];
            float2 v0 = make_float2(acc[mt][nt][0] + bx, acc[mt][nt][1] + by);
            float2 v1 = make_float2(acc[mt][nt][2] + bx, acc[mt][nt][3] + by);
            *(float2*)(p0 + col) = v0;
            *(float2*)(p1 + col) = v1;
        }
    }
}

// ---------------------------------------------------------------------------
// Kernel 3: per-row generalized JSD (beta=0.5, T=1), one CTA per row
// ---------------------------------------------------------------------------
__device__ __forceinline__ void upd(float& m, float& s, float z) {
    if (z <= m) { s += __expf(z - m); }
    else        { s = s * __expf(m - z) + 1.0f; m = z; }
}

__device__ __forceinline__ void merge_ms(float& m, float& s, float m2, float s2) {
    float M = fmaxf(m, m2);
    s = s * __expf(m - M) + s2 * __expf(m2 - M);
    m = M;
}

__device__ __forceinline__ float jsd_term(float zp, float zq, float lse_p, float lse_q) {
    float lp = zp - lse_p, lq = zq - lse_q;
    float p = __expf(lp), q = __expf(lq);
    float lm = __logf(0.5f * (p + q));
    return 0.5f * (p * (lp - lm) + q * (lq - lm));
}

__global__ void __launch_bounds__(256) jsd_kernel(const float* __restrict__ Ls,
                                                  const float* __restrict__ Lt,
                                                  float* __restrict__ row_out)
{
    const int r = blockIdx.x;
    const int tid = threadIdx.x;
    const int wid = tid >> 5, lane = tid & 31;
    const float4* q4 = (const float4*)(Ls + (size_t)r * V);
    const float4* p4 = (const float4*)(Lt + (size_t)r * V);
    constexpr int V4 = V / 4;

    float mp = -1e30f, sp = 0.f, mq = -1e30f, sq = 0.f;
    for (int i = tid; i < V4; i += 256) {
        float4 zp = p4[i], zq = q4[i];
        upd(mp, sp, zp.x); upd(mp, sp, zp.y); upd(mp, sp, zp.z); upd(mp, sp, zp.w);
        upd(mq, sq, zq.x); upd(mq, sq, zq.y); upd(mq, sq, zq.z); upd(mq, sq, zq.w);
    }
#pragma unroll
    for (int o = 16; o; o >>= 1) {
        merge_ms(mp, sp, __shfl_xor_sync(0xffffffffu, mp, o), __shfl_xor_sync(0xffffffffu, sp, o));
        merge_ms(mq, sq, __shfl_xor_sync(0xffffffffu, mq, o), __shfl_xor_sync(0xffffffffu, sq, o));
    }
    __shared__ float rm[2][8], rs[2][8];
    __shared__ float s_lse[2];
    if (lane == 0) { rm[0][wid] = mp; rs[0][wid] = sp; rm[1][wid] = mq; rs[1][wid] = sq; }
    __syncthreads();
    if (tid == 0) {
        float M = rm[0][0], S = rs[0][0];
        for (int w = 1; w < 8; w++) merge_ms(M, S, rm[0][w], rs[0][w]);
        s_lse[0] = M + __logf(S);
        M = rm[1][0]; S = rs[1][0];
        for (int w = 1; w < 8; w++) merge_ms(M, S, rm[1][w], rs[1][w]);
        s_lse[1] = M + __logf(S);
    }
    __syncthreads();
    const float lse_p = s_lse[0], lse_q = s_lse[1];

    float acc = 0.f;
    for (int i = tid; i < V4; i += 256) {
        float4 zp = p4[i], zq = q4[i];
        acc += jsd_term(zp.x, zq.x, lse_p, lse_q);
        acc += jsd_term(zp.y, zq.y, lse_p, lse_q);
        acc += jsd_term(zp.z, zq.z, lse_p, lse_q);
        acc += jsd_term(zp.w, zq.w, lse_p, lse_q);
    }
#pragma unroll
    for (int o = 16; o; o >>= 1) acc += __shfl_xor_sync(0xffffffffu, acc, o);
    __syncthreads();
    if (lane == 0) rm[0][wid] = acc;
    __syncthreads();
    if (tid == 0) {
        float t = 0.f;
        for (int w = 0; w < 8; w++) t += rm[0][w];
        row_out[r] = t;
    }
}

// ---------------------------------------------------------------------------
// Kernel 4: mean over rows -> scalar
// ---------------------------------------------------------------------------
__global__ void __launch_bounds__(256) reduce_kernel(const float* __restrict__ rows,
                                                     float* __restrict__ out) {
    float s = 0.f;
    for (int i = threadIdx.x; i < N_TOK; i += 256) s += rows[i];
#pragma unroll
    for (int o = 16; o; o >>= 1) s += __shfl_xor_sync(0xffffffffu, s, o);
    __shared__ float w[8];
    const int wid = threadIdx.x >> 5, lane = threadIdx.x & 31;
    if (lane == 0) w[wid] = s;
    __syncthreads();
    if (threadIdx.x == 0) {
        float t = 0.f;
        for (int i = 0; i < 8; i++) t += w[i];
        out[0] = t / (float)N_TOK;
    }
}

// ---------------------------------------------------------------------------
// Host
// ---------------------------------------------------------------------------
extern "C" void kernel_launch(void* const* d_in, const int* in_sizes, int n_in,
                              void* d_out, int out_size) {
    (void)in_sizes; (void)n_in; (void)out_size;
    const float* Xs = (const float*)d_in[0];
    const float* Xt = (const float*)d_in[1];
    const float* Ws = (const float*)d_in[2];
    const float* bs = (const float*)d_in[3];
    const float* Wt = (const float*)d_in[4];
    const float* bt = (const float*)d_in[5];

    void *pXs, *pXt, *pWs, *pWt, *pLs, *pLt, *pRows;
    cudaGetSymbolAddress(&pXs, g_Xs);
    cudaGetSymbolAddress(&pXt, g_Xt);
    cudaGetSymbolAddress(&pWs, g_Ws);
    cudaGetSymbolAddress(&pWt, g_Wt);
    cudaGetSymbolAddress(&pLs, g_Ls);
    cudaGetSymbolAddress(&pLt, g_Lt);
    cudaGetSymbolAddress(&pRows, g_rows);

    cudaFuncSetAttribute(gemm_bias_kernel,
                         cudaFuncAttributeMaxDynamicSharedMemorySize, SMEM_BYTES);

    const int nx4 = (N_TOK * H) / 4;
    const int nw4 = (int)(((size_t)V * H) / 4);
    conv_kernel<<<1024, 256>>>(Xs, (__nv_bfloat16*)pXs, nx4);
    conv_kernel<<<1024, 256>>>(Xt, (__nv_bfloat16*)pXt, nx4);
    conv_kernel<<<2048, 256>>>(Ws, (__nv_bfloat16*)pWs, nw4);
    conv_kernel<<<2048, 256>>>(Wt, (__nv_bfloat16*)pWt, nw4);

    dim3 grid(N_TOK / BM, V / BN);   // (16, 125) — mtile fastest for W-panel L2 reuse
    gemm_bias_kernel<<<grid, 256, SMEM_BYTES>>>(
        (const __nv_bfloat16*)pXs, (const __nv_bfloat16*)pWs, bs, (float*)pLs);
    gemm_bias_kernel<<<grid, 256, SMEM_BYTES>>>(
        (const __nv_bfloat16*)pXt, (const __nv_bfloat16*)pWt, bt, (float*)pLt);

    jsd_kernel<<<N_TOK, 256>>>((const float*)pLs, (const float*)pLt, (float*)pRows);
    reduce_kernel<<<1, 256>>>((const float*)pRows, (float*)d_out);
}